// round 5
// baseline (speedup 1.0000x reference)
#include <cuda_runtime.h>
#include <cstdint>

// Problem constants
#define N_VOX   262144      // 8 * 32*32*32 voxels
#define KCODES  256
#define EMB     32
#define SPATIAL 32768       // 32*32*32 voxels per batch
#define CH_STRIDE 32768     // element stride between channels in x / out
#define BATCH_STRIDE 1048576 // 32 channels * 32768
#define OUT_Q_ELEMS 8388608  // 8*32*32768

// ---------------- device-global scratch (allocation-free) ----------------
__device__ double g_commit;
__device__ double g_som;
__device__ unsigned long long g_count;
__device__ int g_encidx[N_VOX];

__global__ void zero_acc_kernel() {
    g_commit = 0.0;
    g_som    = 0.0;
    g_count  = 0ull;
}

// ---------------- packed f32x2 helpers ----------------
__device__ __forceinline__ unsigned long long pack2(float lo, float hi) {
    unsigned long long r;
    asm("mov.b64 %0, {%1, %2};" : "=l"(r) : "f"(lo), "f"(hi));
    return r;
}
__device__ __forceinline__ float2 unpack2(unsigned long long v) {
    float lo, hi;
    asm("mov.b64 {%0, %1}, %2;" : "=f"(lo), "=f"(hi) : "l"(v));
    return make_float2(lo, hi);
}
__device__ __forceinline__ unsigned long long fma2(unsigned long long a,
                                                   unsigned long long b,
                                                   unsigned long long c) {
    unsigned long long r;
    asm("fma.rn.f32x2 %0, %1, %2, %3;" : "=l"(r) : "l"(a), "l"(b), "l"(c));
    return r;
}

// Distance from this thread's x (16 packed f32x2 regs) to codebook row j.
// W rows read from global (L1-resident 32KB) to avoid the 32-way LDS bank
// conflict of per-lane-divergent row reads from a k-major shared tile.
__device__ __forceinline__ float dist_to_row(const float* __restrict__ Wc,
                                             const float* __restrict__ sWsq,
                                             const unsigned long long* xr,
                                             float xsq, int j) {
    const float4* gw = (const float4*)(Wc + j * EMB);
    float dot = 0.f;
#pragma unroll
    for (int i = 0; i < 8; i++) {
        float4 wv = gw[i];
        float2 xa = unpack2(xr[2 * i]);
        float2 xb = unpack2(xr[2 * i + 1]);
        dot += wv.x * xa.x + wv.y * xa.y + wv.z * xb.x + wv.w * xb.y;
    }
    return fmaf(-2.f, dot, xsq + sWsq[j]);
}

// ---------------- main kernel: distances, argmin, out, losses ----------------
__global__ __launch_bounds__(256) void som_main_kernel(
    const float* __restrict__ x,
    const float* __restrict__ Wc,
    float* __restrict__ outq)
{
    __shared__ __align__(16) float sW[KCODES][EMB];  // 32 KB, k-major
    __shared__ float sWsq[KCODES];
    __shared__ float rc[8], rs[8], rn[8];

    const int t = threadIdx.x;

    // cooperative load of codebook: 2048 float4, 8 per thread
    {
        const float4* Wv  = (const float4*)Wc;
        float4*       sWv = (float4*)&sW[0][0];
#pragma unroll
        for (int i = 0; i < 8; i++)
            sWv[t + 256 * i] = Wv[t + 256 * i];
    }
    __syncthreads();
    {
        float s = 0.f;
#pragma unroll
        for (int c = 0; c < EMB; c++) { float v = sW[t][c]; s += v * v; }
        sWsq[t] = s;
    }
    __syncthreads();

    const int n = blockIdx.x * 256 + t;
    const int b = n >> 15;            // batch
    const int sp = n & (SPATIAL - 1); // spatial offset within batch
    const float* xp = x + (size_t)b * BATCH_STRIDE + sp;

    // load x row into 16 packed f32x2 registers; compute ||x||^2
    unsigned long long xr[16];
    float xsq = 0.f;
#pragma unroll
    for (int c = 0; c < EMB; c += 2) {
        float a0 = xp[(size_t)c * CH_STRIDE];
        float a1 = xp[(size_t)(c + 1) * CH_STRIDE];
        xr[c >> 1] = pack2(a0, a1);
        xsq += a0 * a0 + a1 * a1;
    }

    // ---- distance scan over 256 codes (packed fp32x2 FMAs, broadcast LDS) ----
    float best = 3.402823466e38f;
    int   bestk = 0;
#pragma unroll 2
    for (int k = 0; k < KCODES; k++) {
        const ulonglong2* wr = (const ulonglong2*)sW[k];
        unsigned long long acc0 = 0ull, acc1 = 0ull;
#pragma unroll
        for (int i = 0; i < 8; i++) {
            ulonglong2 wv = wr[i];
            acc0 = fma2(xr[2 * i],     wv.x, acc0);
            acc1 = fma2(xr[2 * i + 1], wv.y, acc1);
        }
        float2 a = unpack2(acc0);
        float2 b2 = unpack2(acc1);
        float dot = (a.x + a.y) + (b2.x + b2.y);
        float dist = fmaf(-2.f, dot, xsq + sWsq[k]);
        if (dist < best) { best = dist; bestk = k; }   // first-min tiebreak
    }

    g_encidx[n] = bestk;

    // ---- write quantized output (straight-through == W[bestk]) ----
    {
        float* op = outq + (size_t)b * BATCH_STRIDE + sp;
        const float4* gw = (const float4*)(Wc + bestk * EMB);
#pragma unroll
        for (int i = 0; i < 8; i++) {
            float4 wv = gw[i];
            op[(size_t)(4 * i + 0) * CH_STRIDE] = wv.x;
            op[(size_t)(4 * i + 1) * CH_STRIDE] = wv.y;
            op[(size_t)(4 * i + 2) * CH_STRIDE] = wv.z;
            op[(size_t)(4 * i + 3) * CH_STRIDE] = wv.w;
        }
    }

    // ---- somloss: sum of dist to grid neighbors of bestk (incl. self) ----
    float somv = best;   // self distance == dist[n, bestk]
    int   cnt  = 1;
    const int h = bestk >> 4;
    const int w = bestk & 15;
    if (h > 0)  { somv += dist_to_row(Wc, sWsq, xr, xsq, bestk - 16); cnt++; }
    if (h < 15) { somv += dist_to_row(Wc, sWsq, xr, xsq, bestk + 16); cnt++; }
    if (w > 0)  { somv += dist_to_row(Wc, sWsq, xr, xsq, bestk - 1);  cnt++; }
    if (w < 15) { somv += dist_to_row(Wc, sWsq, xr, xsq, bestk + 1);  cnt++; }

    // commitment per voxel == best distance (||x - W[k*]||^2)
    float cs = best;
    float ss = somv;
    float ns = (float)cnt;

    // ---- block reduction -> double atomics ----
#pragma unroll
    for (int o = 16; o > 0; o >>= 1) {
        cs += __shfl_down_sync(0xffffffffu, cs, o);
        ss += __shfl_down_sync(0xffffffffu, ss, o);
        ns += __shfl_down_sync(0xffffffffu, ns, o);
    }
    const int wid = t >> 5, lid = t & 31;
    if (lid == 0) { rc[wid] = cs; rs[wid] = ss; rn[wid] = ns; }
    __syncthreads();
    if (t == 0) {
        float c = 0.f, s2 = 0.f, nn = 0.f;
#pragma unroll
        for (int i = 0; i < 8; i++) { c += rc[i]; s2 += rs[i]; nn += rn[i]; }
        atomicAdd(&g_commit, (double)c);
        atomicAdd(&g_som,    (double)s2);
        atomicAdd(&g_count,  (unsigned long long)(nn + 0.5f));
    }
}

// ---------------- encodings: one-hot fill, fully coalesced ----------------
// Block covers 4 rows; lane = column => 128B contiguous per warp store.
// Scalar stores because enc base is only 4B-aligned within d_out.
__global__ __launch_bounds__(256) void enc_fill_kernel(float* __restrict__ enc)
{
    const int r0 = blockIdx.x * 4;
    const int c  = threadIdx.x;
#pragma unroll
    for (int q = 0; q < 4; q++) {
        const int r = r0 + q;
        const int k = g_encidx[r];           // broadcast within warp
        enc[(size_t)r * KCODES + c] = (c == k) ? 1.0f : 0.0f;
    }
}

// ---------------- finalize: loss scalar ----------------
__global__ void finalize_kernel(float* __restrict__ out0)
{
    const double commitment = g_commit / (double)OUT_Q_ELEMS;  // mean over N*C
    const double som        = g_som / (double)g_count;
    out0[0] = (float)(6.0 * commitment + 1.0 * som);
}

// ---------------- launch ----------------
extern "C" void kernel_launch(void* const* d_in, const int* in_sizes, int n_in,
                              void* d_out, int out_size)
{
    const float* x  = (const float*)d_in[0];   // [8,32,32,32,32] f32
    const float* Wc = (const float*)d_in[1];   // [256,32] f32
    float* out = (float*)d_out;

    float* loss_ptr = out;                      // 1 element
    float* outq     = out + 1;                  // 8388608 elements
    float* enc      = out + 1 + OUT_Q_ELEMS;    // 67108864 elements

    zero_acc_kernel<<<1, 1>>>();
    som_main_kernel<<<N_VOX / 256, 256>>>(x, Wc, outq);
    enc_fill_kernel<<<N_VOX / 4, 256>>>(enc);
    finalize_kernel<<<1, 1>>>(loss_ptr);
}